// round 4
// baseline (speedup 1.0000x reference)
#include <cuda_runtime.h>
#include <cuda_bf16.h>
#include <cstdint>
#include <math.h>

typedef __nv_bfloat16 bf16;

// ---------- scratch (__device__ globals) ----------
__device__ bf16  g_mag[(size_t)65536 * 544];   // row: t*129+ch, cols 516..543 zeroed each launch
__device__ bf16  g_h1 [(size_t)65536 * 512];
__device__ bf16  g_h2 [(size_t)65536 * 128];
__device__ bf16  g_h3 [(size_t)65536 * 128];   // cols 64..127 are zero
__device__ bf16  g_h4 [(size_t)65536 * 128];
__device__ float g_gates[(size_t)65536 * 384]; // [i,g,o]

__device__ bf16  g_Ws[256 * 320];   // col 2c=real, 2c+1=imag; cols>=258 zero
__device__ bf16  g_W1[544 * 512];
__device__ bf16  g_W2[512 * 128];
__device__ bf16  g_W3[128 * 128];   // out cols >=64 zero
__device__ bf16  g_W4[128 * 128];   // in rows >=64 zero
__device__ bf16  g_W5[128 * 384];
__device__ float g_B1[512];
__device__ float g_B2[128];
__device__ float g_B3[128];
__device__ float g_B4[128];
__device__ float g_B5[384];

// ---------- PTX helpers ----------
__device__ __forceinline__ uint32_t smem_u32(const void* p) {
  return (uint32_t)__cvta_generic_to_shared(p);
}
__device__ __forceinline__ void cp16(uint32_t dst, const void* src) {
  asm volatile("cp.async.cg.shared.global [%0], [%1], 16;\n" :: "r"(dst), "l"(src));
}
__device__ __forceinline__ void cp_commit() { asm volatile("cp.async.commit_group;\n"); }
__device__ __forceinline__ void cp_wait0()  { asm volatile("cp.async.wait_group 0;\n"); }
__device__ __forceinline__ void cp_wait1()  { asm volatile("cp.async.wait_group 1;\n"); }
__device__ __forceinline__ void ldsm4(uint32_t* r, uint32_t a) {
  asm volatile("ldmatrix.sync.aligned.m8n8.x4.shared.b16 {%0,%1,%2,%3}, [%4];\n"
               : "=r"(r[0]), "=r"(r[1]), "=r"(r[2]), "=r"(r[3]) : "r"(a));
}
__device__ __forceinline__ void ldsm4t(uint32_t* r, uint32_t a) {
  asm volatile("ldmatrix.sync.aligned.m8n8.x4.trans.shared.b16 {%0,%1,%2,%3}, [%4];\n"
               : "=r"(r[0]), "=r"(r[1]), "=r"(r[2]), "=r"(r[3]) : "r"(a));
}
__device__ __forceinline__ void mma16816(float* d, const uint32_t* a, const uint32_t* b) {
  asm volatile(
    "mma.sync.aligned.m16n8k16.row.col.f32.bf16.bf16.f32 "
    "{%0,%1,%2,%3}, {%4,%5,%6,%7}, {%8,%9}, {%0,%1,%2,%3};\n"
    : "+f"(d[0]), "+f"(d[1]), "+f"(d[2]), "+f"(d[3])
    : "r"(a[0]), "r"(a[1]), "r"(a[2]), "r"(a[3]), "r"(b[0]), "r"(b[1]));
}
__device__ __forceinline__ float sigf(float x) { return 1.f / (1.f + expf(-x)); }

// ---------- weight folding ----------
__global__ void prep_ws(const float* __restrict__ w) {
  int idx = blockIdx.x * 256 + threadIdx.x;
  if (idx >= 256 * 320) return;
  int k = idx / 320, n = idx - k * 320;
  float v = 0.f;
  if (n < 258) { int c = n >> 1, im = n & 1; v = w[(c + im * 129) * 256 + k]; }
  g_Ws[idx] = __float2bfloat16(v);
}
__global__ void prep_w1(const float* __restrict__ w, const float* __restrict__ b) {
  int idx = blockIdx.x * 256 + threadIdx.x;
  if (idx < 512) g_B1[idx] = b[idx & 127];
  if (idx >= 544 * 512) return;
  int kk = idx >> 9, n = idx & 511;
  int t = n >> 7, o = n & 127;
  float v = 0.f;
  if (kk < 516) {
    int tp = kk / 129, c = kk - tp * 129;
    int j = tp - t + 1;
    if (j >= 0 && j < 3) v = w[o * 387 + c * 3 + j];
  }
  g_W1[idx] = __float2bfloat16(v);
}
__global__ void prep_w2(const float* __restrict__ w, const float* __restrict__ b) {
  int idx = blockIdx.x * 256 + threadIdx.x;
  if (idx < 128) g_B2[idx] = b[idx & 63];
  if (idx >= 512 * 128) return;
  int kk = idx >> 7, n = idx & 127;
  int tin = kk >> 7, cin = kk & 127;
  int tout = n >> 6, o = n & 63;
  int j = tin - 2 * tout + 1;
  float v = (j >= 0 && j < 3) ? w[o * 384 + cin * 3 + j] : 0.f;
  g_W2[idx] = __float2bfloat16(v);
}
__global__ void prep_w3(const float* __restrict__ w, const float* __restrict__ b) {
  int idx = blockIdx.x * 256 + threadIdx.x;
  if (idx < 128) g_B3[idx] = (idx < 64) ? b[idx] : 0.f;
  if (idx >= 128 * 128) return;
  int kk = idx >> 7, o = idx & 127;
  int tin = kk >> 6, c = kk & 63;
  float v = (o < 64) ? w[o * 192 + c * 3 + tin + 1] : 0.f;
  g_W3[idx] = __float2bfloat16(v);
}
__global__ void prep_w4(const float* __restrict__ w, const float* __restrict__ b) {
  int idx = blockIdx.x * 256 + threadIdx.x;
  if (idx < 128) g_B4[idx] = b[idx];
  if (idx >= 128 * 128) return;
  int c = idx >> 7, o = idx & 127;
  float v = (c < 64) ? w[o * 192 + c * 3 + 1] : 0.f;
  g_W4[idx] = __float2bfloat16(v);
}
// gate-major [i, g, o]; f dropped (c0 = 0)
__global__ void prep_w5(const float* __restrict__ wih, const float* __restrict__ bih,
                        const float* __restrict__ bhh) {
  int idx = blockIdx.x * 256 + threadIdx.x;
  if (idx < 384) {
    int r = (idx < 128) ? idx : idx + 128;
    g_B5[idx] = bih[r] + bhh[r];
  }
  if (idx >= 128 * 384) return;
  int c = idx / 384, n = idx - c * 384;
  int r = (n < 128) ? n : n + 128;
  g_W5[idx] = __float2bfloat16(wih[r * 128 + c]);
}
__global__ void zero_magpad() {
  int idx = blockIdx.x * 256 + threadIdx.x;
  if (idx >= 65536 * 28) return;
  int b = idx / 28, c = idx - b * 28;
  g_mag[(size_t)b * 544 + 516 + c] = __float2bfloat16(0.f);
}

// ---------- fused STFT: build windows in smem, full-K A-tile, loop 5 N-subtiles ----------
// grid.x = 2048 (M = 262144 window rows / 128); row m = b*4+t -> x_pad[b][128t+k]
__global__ void __launch_bounds__(256, 2) stft_gemm(const float* __restrict__ data) {
  extern __shared__ __align__(16) bf16 sm[];
  bf16* As = sm;                 // 128 x 264 (pitch 264)
  bf16* Bs = sm + 128 * 264;     // 2 x 32 x 72
  const int tid = threadIdx.x, lane = tid & 31, wid = tid >> 5;
  const int wm = (wid >> 1) * 32, wn = (wid & 1) * 32;
  const long cm = (long)blockIdx.x * 128;
  const long b0 = (long)blockIdx.x * 32;

  // build window tile: 2 rows per iter, 2 cols per thread
  for (int it = 0; it < 64; it++) {
    int row = it * 2 + (tid >> 7);
    long b = b0 + (row >> 2);
    int t = row & 3;
    int c = (tid & 127) * 2;
    int j = t * 128 + c;
    float v0, v1;
    if (j >= 64 && j + 1 < 576) {
      float2 d = *(const float2*)(data + b * 512 + (j - 64));
      v0 = d.x; v1 = d.y;
    } else {
      v0 = (j < 64) ? 0.f : ((j < 576) ? data[b * 512 + j - 64] : data[b * 512 + 1086 - j]);
      int j1 = j + 1;
      v1 = (j1 < 64) ? 0.f : ((j1 < 576) ? data[b * 512 + j1 - 64] : data[b * 512 + 1086 - j1]);
    }
    __nv_bfloat162 hv; hv.x = __float2bfloat16(v0); hv.y = __float2bfloat16(v1);
    *(__nv_bfloat162*)&As[row * 264 + c] = hv;
  }
  __syncthreads();

  const int br = tid >> 3, bc = (tid & 7) * 8;
  for (int ns = 0; ns < 5; ns++) {
    const int cn = ns * 64;
    float acc[2][4][4];
    #pragma unroll
    for (int i = 0; i < 2; i++)
      #pragma unroll
      for (int j = 0; j < 4; j++)
        #pragma unroll
        for (int k = 0; k < 4; k++) acc[i][j][k] = 0.f;

    auto loadB = [&](int bu, int kt) {
      cp16(smem_u32(&Bs[bu * 32 * 72 + br * 72 + bc]),
           g_Ws + (kt * 32 + br) * 320 + cn + bc);
    };
    int buf = 0;
    loadB(0, 0); cp_commit();
    for (int kt = 0; kt < 8; kt++) {
      if (kt + 1 < 8) { loadB(buf ^ 1, kt + 1); cp_commit(); cp_wait1(); }
      else cp_wait0();
      __syncthreads();
      #pragma unroll
      for (int ks = 0; ks < 2; ks++) {
        uint32_t a[2][4], bb[2][4];
        #pragma unroll
        for (int mt = 0; mt < 2; mt++)
          ldsm4(a[mt], smem_u32(&As[(wm + mt * 16 + (lane & 15)) * 264 +
                                    kt * 32 + ks * 16 + (lane >> 4) * 8]));
        #pragma unroll
        for (int q = 0; q < 2; q++) {
          int sel = lane >> 3;
          int krow = ks * 16 + (sel & 1) * 8 + (lane & 7);
          int ncol = wn + q * 16 + (sel >> 1) * 8;
          ldsm4t(bb[q], smem_u32(&Bs[buf * 32 * 72 + krow * 72 + ncol]));
        }
        #pragma unroll
        for (int mt = 0; mt < 2; mt++)
          #pragma unroll
          for (int nt = 0; nt < 4; nt++)
            mma16816(acc[mt][nt], a[mt], &bb[nt >> 1][(nt & 1) * 2]);
      }
      __syncthreads();
      buf ^= 1;
    }
    // magnitude epilogue
    #pragma unroll
    for (int mt = 0; mt < 2; mt++) {
      int r0 = wm + mt * 16 + (lane >> 2);
      #pragma unroll
      for (int nt = 0; nt < 4; nt++) {
        int col = cn + wn + nt * 8 + (lane & 3) * 2;
        if (col < 258) {
          #pragma unroll
          for (int h = 0; h < 2; h++) {
            long row = cm + r0 + h * 8;
            float v0 = acc[mt][nt][h * 2 + 0], v1 = acc[mt][nt][h * 2 + 1];
            long b = row >> 2; int t = (int)(row & 3); int ch = col >> 1;
            g_mag[b * 544 + t * 129 + ch] = __float2bfloat16(sqrtf(v0 * v0 + v1 * v1));
          }
        }
      }
    }
  }
}

// ---------- generic bf16 GEMM: 128x128 CTA, BK=32, 8 warps (4Mx2N), double-buffered ----------
// EPI: 0 = bias+relu->bf16, 2 = bias->f32
template<int EPI>
__global__ void __launch_bounds__(256) gemm2(
    const bf16* __restrict__ A, int lda,
    const bf16* __restrict__ B, int ldb,
    void* __restrict__ Cv, int ldc,
    const float* __restrict__ bias, int K)
{
  __shared__ __align__(16) bf16 As[2][128 * 40];
  __shared__ __align__(16) bf16 Bs[2][32 * 136];
  const int tid = threadIdx.x, lane = tid & 31, wid = tid >> 5;
  const int wm = (wid >> 1) * 32, wn = (wid & 1) * 64;
  const long cm = (long)blockIdx.x * 128;
  const int cn = blockIdx.y * 128;

  const int ar = tid >> 2, ac = (tid & 3) * 8;
  const int br = tid >> 4, bc = (tid & 15) * 8;
  const bf16* Ag = A + (cm + ar) * (long)lda + ac;
  const bf16* Bg = B + (long)br * ldb + cn + bc;

  float acc[2][8][4];
  #pragma unroll
  for (int i = 0; i < 2; i++)
    #pragma unroll
    for (int j = 0; j < 8; j++)
      #pragma unroll
      for (int k = 0; k < 4; k++) acc[i][j][k] = 0.f;

  const int nk = K >> 5;
  auto loadT = [&](int bu, int kt) {
    uint32_t d0 = smem_u32(&As[bu][ar * 40 + ac]);
    cp16(d0, Ag + (long)kt * 32);
    cp16(d0 + 64 * 80, Ag + 64 * (long)lda + (long)kt * 32);
    uint32_t e0 = smem_u32(&Bs[bu][br * 136 + bc]);
    cp16(e0, Bg + (long)kt * 32 * ldb);
    cp16(e0 + 16 * 272, Bg + (long)(kt * 32 + 16) * ldb);
  };

  int buf = 0;
  loadT(0, 0); cp_commit();
  for (int kt = 0; kt < nk; kt++) {
    if (kt + 1 < nk) { loadT(buf ^ 1, kt + 1); cp_commit(); cp_wait1(); }
    else cp_wait0();
    __syncthreads();
    #pragma unroll
    for (int ks = 0; ks < 2; ks++) {
      uint32_t a[2][4], bb[4][4];
      #pragma unroll
      for (int mt = 0; mt < 2; mt++)
        ldsm4(a[mt], smem_u32(&As[buf][(wm + mt * 16 + (lane & 15)) * 40 +
                                       ks * 16 + (lane >> 4) * 8]));
      #pragma unroll
      for (int q = 0; q < 4; q++) {
        int sel = lane >> 3;
        int krow = ks * 16 + (sel & 1) * 8 + (lane & 7);
        int ncol = wn + q * 16 + (sel >> 1) * 8;
        ldsm4t(bb[q], smem_u32(&Bs[buf][krow * 136 + ncol]));
      }
      #pragma unroll
      for (int mt = 0; mt < 2; mt++)
        #pragma unroll
        for (int nt = 0; nt < 8; nt++)
          mma16816(acc[mt][nt], a[mt], &bb[nt >> 1][(nt & 1) * 2]);
    }
    __syncthreads();
    buf ^= 1;
  }

  #pragma unroll
  for (int mt = 0; mt < 2; mt++) {
    int r0 = wm + mt * 16 + (lane >> 2);
    #pragma unroll
    for (int nt = 0; nt < 8; nt++) {
      int col = cn + wn + nt * 8 + (lane & 3) * 2;
      #pragma unroll
      for (int h = 0; h < 2; h++) {
        long row = cm + r0 + h * 8;
        float v0 = acc[mt][nt][h * 2 + 0], v1 = acc[mt][nt][h * 2 + 1];
        if (EPI == 0) {
          __nv_bfloat162 hv;
          hv.x = __float2bfloat16(fmaxf(v0 + bias[col], 0.f));
          hv.y = __float2bfloat16(fmaxf(v1 + bias[col + 1], 0.f));
          *(__nv_bfloat162*)((bf16*)Cv + row * (long)ldc + col) = hv;
        } else {
          *(float2*)((float*)Cv + row * (long)ldc + col) =
              make_float2(v0 + bias[col], v1 + bias[col + 1]);
        }
      }
    }
  }
}

// ---------- fused LSTM cell (h0=c0=0, f dropped) + decoder dot + sigmoid ----------
__global__ void lstm_dec(const float* __restrict__ dec_w, const float* __restrict__ dec_b,
                         float* __restrict__ out) {
  int b = blockIdx.x, j = threadIdx.x;
  const float* g = g_gates + (size_t)b * 384;
  float gi = g[j], gg = g[j + 128], go = g[j + 256];
  float c = sigf(gi) * tanhf(gg);
  float h = sigf(go) * tanhf(c);
  float v = dec_w[j] * fmaxf(h, 0.f);
  #pragma unroll
  for (int s = 16; s; s >>= 1) v += __shfl_xor_sync(0xffffffffu, v, s);
  __shared__ float red[4];
  if ((j & 31) == 0) red[j >> 5] = v;
  __syncthreads();
  if (j == 0) out[b] = sigf(red[0] + red[1] + red[2] + red[3] + dec_b[0]);
}

extern "C" void kernel_launch(void* const* d_in, const int* in_sizes, int n_in,
                              void* d_out, int out_size) {
  const float* data   = (const float*)d_in[0];
  const float* stft_w = (const float*)d_in[2];
  const float* e1_w   = (const float*)d_in[3];
  const float* e1_b   = (const float*)d_in[4];
  const float* e2_w   = (const float*)d_in[5];
  const float* e2_b   = (const float*)d_in[6];
  const float* e3_w   = (const float*)d_in[7];
  const float* e3_b   = (const float*)d_in[8];
  const float* e4_w   = (const float*)d_in[9];
  const float* e4_b   = (const float*)d_in[10];
  const float* w_ih   = (const float*)d_in[11];
  const float* b_ih   = (const float*)d_in[13];
  const float* b_hh   = (const float*)d_in[14];
  const float* dec_w  = (const float*)d_in[15];
  const float* dec_b  = (const float*)d_in[16];
  float* out = (float*)d_out;

  void *pmag, *ph1, *ph2, *ph3, *ph4, *pgat;
  void *pW1, *pW2, *pW3, *pW4, *pW5, *pB1, *pB2, *pB3, *pB4, *pB5;
  cudaGetSymbolAddress(&pmag, g_mag);
  cudaGetSymbolAddress(&ph1, g_h1); cudaGetSymbolAddress(&ph2, g_h2);
  cudaGetSymbolAddress(&ph3, g_h3); cudaGetSymbolAddress(&ph4, g_h4);
  cudaGetSymbolAddress(&pgat, g_gates);
  cudaGetSymbolAddress(&pW1, g_W1); cudaGetSymbolAddress(&pW2, g_W2);
  cudaGetSymbolAddress(&pW3, g_W3); cudaGetSymbolAddress(&pW4, g_W4);
  cudaGetSymbolAddress(&pW5, g_W5);
  cudaGetSymbolAddress(&pB1, g_B1); cudaGetSymbolAddress(&pB2, g_B2);
  cudaGetSymbolAddress(&pB3, g_B3); cudaGetSymbolAddress(&pB4, g_B4);
  cudaGetSymbolAddress(&pB5, g_B5);

  static int smem_set = 0;
  if (!smem_set) {
    cudaFuncSetAttribute(stft_gemm, cudaFuncAttributeMaxDynamicSharedMemorySize, 76800);
    smem_set = 1;
  }

  prep_ws<<<(256 * 320 + 255) / 256, 256>>>(stft_w);
  prep_w1<<<(544 * 512 + 255) / 256, 256>>>(e1_w, e1_b);
  prep_w2<<<(512 * 128 + 255) / 256, 256>>>(e2_w, e2_b);
  prep_w3<<<64, 256>>>(e3_w, e3_b);
  prep_w4<<<64, 256>>>(e4_w, e4_b);
  prep_w5<<<192, 256>>>(w_ih, b_ih, b_hh);
  zero_magpad<<<(65536 * 28 + 255) / 256, 256>>>();

  stft_gemm<<<2048, 256, 76800>>>(data);

  gemm2<0><<<dim3(512, 4), 256>>>((const bf16*)pmag, 544, (const bf16*)pW1, 512,
                                  ph1, 512, (const float*)pB1, 544);
  gemm2<0><<<dim3(512, 1), 256>>>((const bf16*)ph1, 512, (const bf16*)pW2, 128,
                                  ph2, 128, (const float*)pB2, 512);
  gemm2<0><<<dim3(512, 1), 256>>>((const bf16*)ph2, 128, (const bf16*)pW3, 128,
                                  ph3, 128, (const float*)pB3, 128);
  gemm2<0><<<dim3(512, 1), 256>>>((const bf16*)ph3, 128, (const bf16*)pW4, 128,
                                  ph4, 128, (const float*)pB4, 128);
  gemm2<2><<<dim3(512, 3), 256>>>((const bf16*)ph4, 128, (const bf16*)pW5, 384,
                                  pgat, 384, (const float*)pB5, 128);
  lstm_dec<<<65536, 128>>>(dec_w, dec_b, out);
}

// round 8
// speedup vs baseline: 1.0460x; 1.0460x over previous
#include <cuda_runtime.h>
#include <cuda_bf16.h>
#include <cstdint>
#include <math.h>

typedef __nv_bfloat16 bf16;

// ---------- scratch ----------
__device__ bf16 g_mag[(size_t)65536 * 576];   // pitch 576 = K of e1; cols 516.. stay BSS-zero
__device__ bf16 g_h1 [(size_t)65536 * 512];
__device__ bf16 g_h2 [(size_t)65536 * 128];
__device__ bf16 g_h3 [(size_t)65536 * 128];
__device__ bf16 g_h4 [(size_t)65536 * 128];
__device__ bf16 g_gates[(size_t)65536 * 384]; // [i,g,o] bf16

// weights K-major: W[k][n]
__device__ bf16 g_Ws[256 * 320];
__device__ bf16 g_W1[576 * 512];
__device__ bf16 g_W2[512 * 128];
__device__ bf16 g_W3[128 * 128];
__device__ bf16 g_W4[128 * 128];
__device__ bf16 g_W5[128 * 384];
__device__ float g_B1[512];
__device__ float g_B2[128];
__device__ float g_B3[128];
__device__ float g_B4[128];
__device__ float g_B5[384];

// ---------- helpers ----------
__device__ __forceinline__ uint32_t smem_u32(const void* p) {
  return (uint32_t)__cvta_generic_to_shared(p);
}
__device__ __forceinline__ void cp16(uint32_t dst, const void* src) {
  asm volatile("cp.async.cg.shared.global [%0], [%1], 16;\n" :: "r"(dst), "l"(src));
}
__device__ __forceinline__ void cp_commit() { asm volatile("cp.async.commit_group;\n"); }
__device__ __forceinline__ void cp_wait0()  { asm volatile("cp.async.wait_group 0;\n"); }
__device__ __forceinline__ void cp_wait1()  { asm volatile("cp.async.wait_group 1;\n"); }
__device__ __forceinline__ void ldsm4(uint32_t* r, uint32_t a) {
  asm volatile("ldmatrix.sync.aligned.m8n8.x4.shared.b16 {%0,%1,%2,%3}, [%4];\n"
               : "=r"(r[0]), "=r"(r[1]), "=r"(r[2]), "=r"(r[3]) : "r"(a));
}
__device__ __forceinline__ void ldsm4t(uint32_t* r, uint32_t a) {
  asm volatile("ldmatrix.sync.aligned.m8n8.x4.trans.shared.b16 {%0,%1,%2,%3}, [%4];\n"
               : "=r"(r[0]), "=r"(r[1]), "=r"(r[2]), "=r"(r[3]) : "r"(a));
}
__device__ __forceinline__ void mma16816(float* d, const uint32_t* a, const uint32_t* b) {
  asm volatile(
    "mma.sync.aligned.m16n8k16.row.col.f32.bf16.bf16.f32 "
    "{%0,%1,%2,%3}, {%4,%5,%6,%7}, {%8,%9}, {%0,%1,%2,%3};\n"
    : "+f"(d[0]), "+f"(d[1]), "+f"(d[2]), "+f"(d[3])
    : "r"(a[0]), "r"(a[1]), "r"(a[2]), "r"(a[3]), "r"(b[0]), "r"(b[1]));
}
__device__ __forceinline__ float sigf(float x) { return 1.f / (1.f + expf(-x)); }

// ---------- merged weight prep ----------
__global__ void prep_all(const float* __restrict__ stw,
    const float* __restrict__ w1, const float* __restrict__ b1,
    const float* __restrict__ w2, const float* __restrict__ b2,
    const float* __restrict__ w3, const float* __restrict__ b3,
    const float* __restrict__ w4, const float* __restrict__ b4,
    const float* __restrict__ wih, const float* __restrict__ bih,
    const float* __restrict__ bhh) {
  int idx = blockIdx.x * 256 + threadIdx.x;
  if (idx < 81920) {                       // Ws[k*320+n]
    int k = idx / 320, n = idx - k * 320; float v = 0.f;
    if (n < 258) { int c = n >> 1, im = n & 1; v = stw[(c + im * 129) * 256 + k]; }
    g_Ws[idx] = __float2bfloat16(v); return;
  }
  idx -= 81920;
  if (idx < 294912) {                      // W1[kk*512+n], kk<576
    int kk = idx >> 9, n = idx & 511;
    int t = n >> 7, o = n & 127; float v = 0.f;
    if (kk < 516) {
      int tp = kk / 129, c = kk - tp * 129, j = tp - t + 1;
      if (j >= 0 && j < 3) v = w1[o * 387 + c * 3 + j];
    }
    g_W1[idx] = __float2bfloat16(v); return;
  }
  idx -= 294912;
  if (idx < 65536) {                       // W2[kk*128+n]
    int kk = idx >> 7, n = idx & 127;
    int tout = n >> 6, o = n & 63, tin = kk >> 7, cin = kk & 127;
    int j = tin - 2 * tout + 1;
    g_W2[idx] = __float2bfloat16((j >= 0 && j < 3) ? w2[o * 384 + cin * 3 + j] : 0.f);
    return;
  }
  idx -= 65536;
  if (idx < 16384) {                       // W3[kk*128+n]
    int kk = idx >> 7, n = idx & 127, tin = kk >> 6, c = kk & 63;
    g_W3[idx] = __float2bfloat16((n < 64) ? w3[n * 192 + c * 3 + tin + 1] : 0.f);
    return;
  }
  idx -= 16384;
  if (idx < 16384) {                       // W4[kk*128+n]
    int kk = idx >> 7, n = idx & 127;
    g_W4[idx] = __float2bfloat16((kk < 64) ? w4[n * 192 + kk * 3 + 1] : 0.f);
    return;
  }
  idx -= 16384;
  if (idx < 49152) {                       // W5[c*384+nn]
    int c = idx / 384, nn = idx - c * 384;
    int r = (nn < 128) ? nn : nn + 128;
    g_W5[idx] = __float2bfloat16(wih[r * 128 + c]); return;
  }
  idx -= 49152;
  if (idx < 512) { g_B1[idx] = b1[idx & 127]; return; }
  idx -= 512;
  if (idx < 128) { g_B2[idx] = b2[idx & 63]; return; }
  idx -= 128;
  if (idx < 128) { g_B3[idx] = (idx < 64) ? b3[idx] : 0.f; return; }
  idx -= 128;
  if (idx < 128) { g_B4[idx] = b4[idx]; return; }
  idx -= 128;
  if (idx < 384) { int r = (idx < 128) ? idx : idx + 128; g_B5[idx] = bih[r] + bhh[r]; }
}

// ---------- STFT: windows in smem, full-K A; per N-subtile load B once, 0 inner barriers ----------
__global__ void __launch_bounds__(256, 2) stft_gemm(const float* __restrict__ data) {
  extern __shared__ __align__(16) char sm[];
  bf16* As = (bf16*)sm;                 // 128 x 264
  bf16* Bs = (bf16*)sm + 128 * 264;     // 256 x 72
  const int tid = threadIdx.x, lane = tid & 31, wid = tid >> 5;
  const int wm = (wid >> 1) * 32, wn = (wid & 1) * 32;
  const long cm = (long)blockIdx.x * 128;
  const long b0 = (long)blockIdx.x * 32;

  for (int it = 0; it < 64; it++) {
    int row = it * 2 + (tid >> 7);
    long b = b0 + (row >> 2);
    int t = row & 3, c = (tid & 127) * 2, j = t * 128 + c;
    float v0, v1;
    if (j >= 64 && j + 1 < 576) {
      float2 d = *(const float2*)(data + b * 512 + (j - 64));
      v0 = d.x; v1 = d.y;
    } else {
      v0 = (j < 64) ? 0.f : ((j < 576) ? data[b * 512 + j - 64] : data[b * 512 + 1086 - j]);
      int j1 = j + 1;
      v1 = (j1 < 64) ? 0.f : ((j1 < 576) ? data[b * 512 + j1 - 64] : data[b * 512 + 1086 - j1]);
    }
    __nv_bfloat162 hv; hv.x = __float2bfloat16(v0); hv.y = __float2bfloat16(v1);
    *(__nv_bfloat162*)&As[row * 264 + c] = hv;
  }

  for (int ns = 0; ns < 5; ns++) {
    const int cn = ns * 64;
    float acc[2][4][4];
    #pragma unroll
    for (int i = 0; i < 2; i++)
      #pragma unroll
      for (int j = 0; j < 4; j++)
        #pragma unroll
        for (int k = 0; k < 4; k++) acc[i][j][k] = 0.f;

    __syncthreads();  // prior compute / window build done before (re)filling Bs
    #pragma unroll
    for (int i = 0; i < 8; i++) {
      int o = tid + i * 256;
      int r = o >> 3, c8 = (o & 7) * 8;
      cp16(smem_u32(&Bs[r * 72 + c8]), g_Ws + r * 320 + cn + c8);
    }
    cp_commit(); cp_wait0();
    __syncthreads();

    #pragma unroll
    for (int kt = 0; kt < 8; kt++) {
      #pragma unroll
      for (int ks = 0; ks < 2; ks++) {
        uint32_t a[2][4], bb[2][4];
        #pragma unroll
        for (int mt = 0; mt < 2; mt++)
          ldsm4(a[mt], smem_u32(&As[(wm + mt * 16 + (lane & 15)) * 264 +
                                    kt * 32 + ks * 16 + (lane >> 4) * 8]));
        #pragma unroll
        for (int q = 0; q < 2; q++) {
          int sel = lane >> 3;
          int krow = kt * 32 + ks * 16 + (sel & 1) * 8 + (lane & 7);
          int ncol = wn + q * 16 + (sel >> 1) * 8;
          ldsm4t(bb[q], smem_u32(&Bs[krow * 72 + ncol]));
        }
        #pragma unroll
        for (int mt = 0; mt < 2; mt++)
          #pragma unroll
          for (int nt = 0; nt < 4; nt++)
            mma16816(acc[mt][nt], a[mt], &bb[nt >> 1][(nt & 1) * 2]);
      }
    }
    #pragma unroll
    for (int mt = 0; mt < 2; mt++) {
      int r0 = wm + mt * 16 + (lane >> 2);
      #pragma unroll
      for (int nt = 0; nt < 4; nt++) {
        int col = cn + wn + nt * 8 + (lane & 3) * 2;
        if (col < 258) {
          #pragma unroll
          for (int h = 0; h < 2; h++) {
            long row = cm + r0 + h * 8;
            float v0 = acc[mt][nt][h * 2 + 0], v1 = acc[mt][nt][h * 2 + 1];
            long b = row >> 2; int t = (int)(row & 3); int ch = col >> 1;
            g_mag[b * 576 + t * 129 + ch] = __float2bfloat16(sqrtf(v0 * v0 + v1 * v1));
          }
        }
      }
    }
  }
}

// ---------- dense GEMM: 128x128 tile, BK=64 double-buffered ----------
// EPI 0: bias+relu -> bf16 ; EPI 3: bias -> bf16 (no relu)
template<int NTOT, int K, int EPI>
__global__ void __launch_bounds__(256, 2) gemm3(
    const bf16* __restrict__ A, const bf16* __restrict__ B,
    bf16* __restrict__ C, const float* __restrict__ bias) {
  constexpr int NC = K / 64;
  extern __shared__ __align__(16) char sm[];
  bf16* As = (bf16*)sm;                       // 2 x 128 x 72
  bf16* Bs = (bf16*)sm + 2 * 128 * 72;        // 2 x 64 x 136
  const int tid = threadIdx.x, lane = tid & 31, wid = tid >> 5;
  const int wm = (wid >> 1) * 32, wn = (wid & 1) * 64;
  const long cm = (long)blockIdx.x * 128;
  const int cn = blockIdx.y * 128;

  float acc[2][8][4];
  #pragma unroll
  for (int i = 0; i < 2; i++)
    #pragma unroll
    for (int j = 0; j < 8; j++)
      #pragma unroll
      for (int k = 0; k < 4; k++) acc[i][j][k] = 0.f;

  auto load = [&](int buf, int kc) {
    bf16* Ad = As + buf * 128 * 72;
    #pragma unroll
    for (int i = 0; i < 4; i++) {
      int o = tid + i * 256;
      int r = o >> 3, c8 = (o & 7) * 8;
      cp16(smem_u32(&Ad[r * 72 + c8]), A + (cm + r) * (long)K + kc * 64 + c8);
    }
    bf16* Bd = Bs + buf * 64 * 136;
    #pragma unroll
    for (int i = 0; i < 4; i++) {
      int o = tid + i * 256;
      int r = o >> 4, c8 = (o & 15) * 8;
      cp16(smem_u32(&Bd[r * 136 + c8]), B + (long)(kc * 64 + r) * NTOT + cn + c8);
    }
  };

  load(0, 0); cp_commit();
  for (int kc = 0; kc < NC; kc++) {
    int buf = kc & 1;
    if (kc + 1 < NC) { load(buf ^ 1, kc + 1); cp_commit(); cp_wait1(); }
    else cp_wait0();
    __syncthreads();
    bf16* Ab = As + buf * 128 * 72;
    bf16* Bb = Bs + buf * 64 * 136;
    #pragma unroll
    for (int ks = 0; ks < 4; ks++) {
      uint32_t a[2][4], bb[4][4];
      #pragma unroll
      for (int mt = 0; mt < 2; mt++)
        ldsm4(a[mt], smem_u32(&Ab[(wm + mt * 16 + (lane & 15)) * 72 +
                                  ks * 16 + (lane >> 4) * 8]));
      #pragma unroll
      for (int q = 0; q < 4; q++) {
        int sel = lane >> 3;
        int krow = ks * 16 + (sel & 1) * 8 + (lane & 7);
        int ncol = wn + q * 16 + (sel >> 1) * 8;
        ldsm4t(bb[q], smem_u32(&Bb[krow * 136 + ncol]));
      }
      #pragma unroll
      for (int mt = 0; mt < 2; mt++)
        #pragma unroll
        for (int nt = 0; nt < 8; nt++)
          mma16816(acc[mt][nt], a[mt], &bb[nt >> 1][(nt & 1) * 2]);
    }
    __syncthreads();
  }

  #pragma unroll
  for (int mt = 0; mt < 2; mt++) {
    int r0 = wm + mt * 16 + (lane >> 2);
    #pragma unroll
    for (int nt = 0; nt < 8; nt++) {
      int col = cn + wn + nt * 8 + (lane & 3) * 2;
      #pragma unroll
      for (int h = 0; h < 2; h++) {
        long row = cm + r0 + h * 8;
        float v0 = acc[mt][nt][h * 2 + 0] + bias[col];
        float v1 = acc[mt][nt][h * 2 + 1] + bias[col + 1];
        if (EPI == 0) { v0 = fmaxf(v0, 0.f); v1 = fmaxf(v1, 0.f); }
        __nv_bfloat162 hv; hv.x = __float2bfloat16(v0); hv.y = __float2bfloat16(v1);
        *(__nv_bfloat162*)(C + row * (long)NTOT + col) = hv;
      }
    }
  }
}

// ---------- LSTM cell (h0=c0=0, f dropped) + decoder ----------
__global__ void lstm_dec(const float* __restrict__ dec_w, const float* __restrict__ dec_b,
                         float* __restrict__ out) {
  int b = blockIdx.x, j = threadIdx.x;
  const bf16* g = g_gates + (size_t)b * 384;
  float gi = __bfloat162float(g[j]);
  float gg = __bfloat162float(g[j + 128]);
  float go = __bfloat162float(g[j + 256]);
  float c = sigf(gi) * tanhf(gg);
  float h = sigf(go) * tanhf(c);
  float v = dec_w[j] * fmaxf(h, 0.f);
  #pragma unroll
  for (int s = 16; s; s >>= 1) v += __shfl_xor_sync(0xffffffffu, v, s);
  __shared__ float red[4];
  if ((j & 31) == 0) red[j >> 5] = v;
  __syncthreads();
  if (j == 0) out[b] = sigf(red[0] + red[1] + red[2] + red[3] + dec_b[0]);
}

extern "C" void kernel_launch(void* const* d_in, const int* in_sizes, int n_in,
                              void* d_out, int out_size) {
  const float* data = (const float*)d_in[0];
  const float* stw  = (const float*)d_in[2];
  const float* e1w  = (const float*)d_in[3];
  const float* e1b  = (const float*)d_in[4];
  const float* e2w  = (const float*)d_in[5];
  const float* e2b  = (const float*)d_in[6];
  const float* e3w  = (const float*)d_in[7];
  const float* e3b  = (const float*)d_in[8];
  const float* e4w  = (const float*)d_in[9];
  const float* e4b  = (const float*)d_in[10];
  const float* wih  = (const float*)d_in[11];
  const float* bih  = (const float*)d_in[13];
  const float* bhh  = (const float*)d_in[14];
  const float* decw = (const float*)d_in[15];
  const float* decb = (const float*)d_in[16];
  float* out = (float*)d_out;

  void *pmag, *ph1, *ph2, *ph3, *ph4, *pgat, *pW1, *pW2, *pW3, *pW4, *pW5;
  void *pB1, *pB2, *pB3, *pB4, *pB5;
  cudaGetSymbolAddress(&pmag, g_mag);
  cudaGetSymbolAddress(&ph1, g_h1); cudaGetSymbolAddress(&ph2, g_h2);
  cudaGetSymbolAddress(&ph3, g_h3); cudaGetSymbolAddress(&ph4, g_h4);
  cudaGetSymbolAddress(&pgat, g_gates);
  cudaGetSymbolAddress(&pW1, g_W1); cudaGetSymbolAddress(&pW2, g_W2);
  cudaGetSymbolAddress(&pW3, g_W3); cudaGetSymbolAddress(&pW4, g_W4);
  cudaGetSymbolAddress(&pW5, g_W5);
  cudaGetSymbolAddress(&pB1, g_B1); cudaGetSymbolAddress(&pB2, g_B2);
  cudaGetSymbolAddress(&pB3, g_B3); cudaGetSymbolAddress(&pB4, g_B4);
  cudaGetSymbolAddress(&pB5, g_B5);

  const int STFT_SMEM = (128 * 264 + 256 * 72) * 2;          // 104448
  const int G3_SMEM   = (2 * 128 * 72 + 2 * 64 * 136) * 2;   // 71680
  cudaFuncSetAttribute(stft_gemm, cudaFuncAttributeMaxDynamicSharedMemorySize, STFT_SMEM);
  cudaFuncSetAttribute(gemm3<512, 576, 0>, cudaFuncAttributeMaxDynamicSharedMemorySize, G3_SMEM);
  cudaFuncSetAttribute(gemm3<128, 512, 0>, cudaFuncAttributeMaxDynamicSharedMemorySize, G3_SMEM);
  cudaFuncSetAttribute(gemm3<128, 128, 0>, cudaFuncAttributeMaxDynamicSharedMemorySize, G3_SMEM);
  cudaFuncSetAttribute(gemm3<384, 128, 3>, cudaFuncAttributeMaxDynamicSharedMemorySize, G3_SMEM);

  prep_all<<<2054, 256>>>(stw, e1w, e1b, e2w, e2b, e3w, e3b, e4w, e4b, wih, bih, bhh);
  stft_gemm<<<2048, 256, STFT_SMEM>>>(data);
  gemm3<512, 576, 0><<<dim3(512, 4), 256, G3_SMEM>>>((const bf16*)pmag, (const bf16*)pW1,
                                                     (bf16*)ph1, (const float*)pB1);
  gemm3<128, 512, 0><<<dim3(512, 1), 256, G3_SMEM>>>((const bf16*)ph1, (const bf16*)pW2,
                                                     (bf16*)ph2, (const float*)pB2);
  gemm3<128, 128, 0><<<dim3(512, 1), 256, G3_SMEM>>>((const bf16*)ph2, (const bf16*)pW3,
                                                     (bf16*)ph3, (const float*)pB3);
  gemm3<128, 128, 0><<<dim3(512, 1), 256, G3_SMEM>>>((const bf16*)ph3, (const bf16*)pW4,
                                                     (bf16*)ph4, (const float*)pB4);
  gemm3<384, 128, 3><<<dim3(512, 3), 256, G3_SMEM>>>((const bf16*)ph4, (const bf16*)pW5,
                                                     (bf16*)pgat, (const float*)pB5);
  lstm_dec<<<65536, 128>>>(decw, decb, out);
}